// round 12
// baseline (speedup 1.0000x reference)
#include <cuda_runtime.h>
#include <cstdint>
#include <cstddef>

#define B_  256
#define L_  2048
#define H_  128
#define H2_ 256
#define V_  32000
#define TB  64        // tokens per encode block

// ---------------- scratch (static device globals; no allocs allowed) ----------------
__device__ float g_h[(size_t)B_ * L_ * H_];   // encoded h_all [B,L,H]
__device__ float g_r[B_ * H_];
__device__ float g_r2[B_ * H_];

// ============ packed f32x2 helpers (FFMA2 — Blackwell, PTX-only path) ============
__device__ __forceinline__ uint64_t pk2(float lo, float hi) {
    uint64_t r;
    asm("mov.b64 %0, {%1, %2};" : "=l"(r) : "f"(lo), "f"(hi));
    return r;
}
__device__ __forceinline__ void upk2(uint64_t v, float& lo, float& hi) {
    asm("mov.b64 {%0, %1}, %2;" : "=f"(lo), "=f"(hi) : "l"(v));
}
__device__ __forceinline__ uint64_t fma2(uint64_t a, uint64_t b, uint64_t c) {
    uint64_t d;
    asm("fma.rn.f32x2 %0, %1, %2, %3;" : "=l"(d) : "l"(a), "l"(b), "l"(c));
    return d;
}

// ---------------- profiling-alignment dummies ----------------
__global__ void dummy_kernel() {}

// =====================================================================
// Encode (FFMA2, LDS.64, double-buffered weight chunks).
// Arithmetic chains identical to R1 -> bit-identical output.
// 64 tokens/CTA, 256 threads.
// =====================================================================
#define ENC_SMEM ((64 * 132 + 64 * 260 + 2 * 8192) * 4)   // 165888 B

__global__ void __launch_bounds__(256, 1) encode_ffma2(
    const int*   __restrict__ seq,   const float* __restrict__ embed,
    const float* __restrict__ W1,    const float* __restrict__ b1,
    const float* __restrict__ W2,    const float* __restrict__ b2,
    const float* __restrict__ gamma, const float* __restrict__ beta)
{
    extern __shared__ float sm[];
    float* Es  = sm;                 // [64][132]
    float* Us  = Es + 64 * 132;      // [64][260] (u), reused as y [64][132]
    float* Wb0 = Us + 64 * 260;      // weight buffer 0 (8192 floats)
    float* Wb1 = Wb0 + 8192;         // weight buffer 1

    const int tid = threadIdx.x;
    const int ty  = tid >> 4;        // 0..15
    const int tx  = tid & 15;        // 0..15
    const int tok0 = blockIdx.x * TB;

    // ---- gather embeddings (float4) ----
    for (int i = tid; i < TB * 32; i += 256) {
        int row = i >> 5, q = i & 31;
        int s = seq[tok0 + row];
        float4 v = *(const float4*)(embed + (size_t)s * H_ + 4 * q);
        *(float4*)(Es + row * 132 + 4 * q) = v;
    }

    // prologue: W1 chunk 0 -> Wb0
    {
        const float4* src = (const float4*)(W1);
        for (int i = tid; i < 2048; i += 256) ((float4*)Wb0)[i] = src[i];
    }

    // ---- GEMM1: u = relu(e @ W1 + b1)   (64x256, K=128), DB chunks of 32 ----
    uint64_t acc[4][8];
    #pragma unroll
    for (int r = 0; r < 4; r++)
        #pragma unroll
        for (int j = 0; j < 8; j++) acc[r][j] = 0ull;

    for (int c = 0; c < 4; c++) {
        __syncthreads();                         // chunk c writes visible; buf (c+1)&1 free
        if (c + 1 < 4) {                         // prefetch next chunk
            const float4* src = (const float4*)(W1 + (c + 1) * 32 * H2_);
            float4* dst = (float4*)(((c + 1) & 1) ? Wb1 : Wb0);
            for (int i = tid; i < 2048; i += 256) dst[i] = src[i];
        }
        const float* Wc = (c & 1) ? Wb1 : Wb0;
        const int kc = c * 32;
        #pragma unroll 8
        for (int kk = 0; kk < 32; kk++) {
            uint64_t a2[4], b2v[8];
            #pragma unroll
            for (int r = 0; r < 4; r++) {
                float a = Es[(ty * 4 + r) * 132 + kc + kk];
                a2[r] = pk2(a, a);
            }
            #pragma unroll
            for (int j = 0; j < 8; j++) {
                float2 bw = *(const float2*)(Wc + kk * H2_ + 32 * j + 2 * tx);
                b2v[j] = pk2(bw.x, bw.y);
            }
            #pragma unroll
            for (int r = 0; r < 4; r++)
                #pragma unroll
                for (int j = 0; j < 8; j++) acc[r][j] = fma2(a2[r], b2v[j], acc[r][j]);
        }
    }
    // epilogue GEMM1 (own data; no barrier needed before)
    #pragma unroll
    for (int r = 0; r < 4; r++)
        #pragma unroll
        for (int j = 0; j < 8; j++) {
            float x0, x1;
            upk2(acc[r][j], x0, x1);
            int col0 = 32 * j + 2 * tx;
            float2 bb = *(const float2*)(b1 + col0);
            float2 uo;
            uo.x = fmaxf(x0 + bb.x, 0.f);
            uo.y = fmaxf(x1 + bb.y, 0.f);
            *(float2*)(Us + (ty * 4 + r) * 260 + col0) = uo;
        }
    // prologue GEMM2: W2 chunk 0 -> Wb0 (safe: last Wb0 reads finished before c=3 barrier)
    {
        const float4* src = (const float4*)(W2);
        for (int i = tid; i < 1024; i += 256) ((float4*)Wb0)[i] = src[i];
    }

    // ---- GEMM2: y = u @ W2 + b2 + e   (64x128, K=256), DB chunks of 32 ----
    uint64_t acc2[4][4];
    #pragma unroll
    for (int r = 0; r < 4; r++)
        #pragma unroll
        for (int j = 0; j < 4; j++) acc2[r][j] = 0ull;

    for (int c2 = 0; c2 < 8; c2++) {
        __syncthreads();                         // Us + chunk c2 visible; other buf free
        if (c2 + 1 < 8) {
            const float4* src = (const float4*)(W2 + (c2 + 1) * 32 * H_);
            float4* dst = (float4*)(((c2 + 1) & 1) ? Wb1 : Wb0);
            for (int i = tid; i < 1024; i += 256) dst[i] = src[i];
        }
        const float* Wc = (c2 & 1) ? Wb1 : Wb0;
        const int kc = c2 * 32;
        #pragma unroll 8
        for (int kk = 0; kk < 32; kk++) {
            uint64_t a2[4], b2v[4];
            #pragma unroll
            for (int r = 0; r < 4; r++) {
                float a = Us[(ty * 4 + r) * 260 + kc + kk];
                a2[r] = pk2(a, a);
            }
            #pragma unroll
            for (int j = 0; j < 4; j++) {
                float2 bw = *(const float2*)(Wc + kk * H_ + 32 * j + 2 * tx);
                b2v[j] = pk2(bw.x, bw.y);
            }
            #pragma unroll
            for (int r = 0; r < 4; r++)
                #pragma unroll
                for (int j = 0; j < 4; j++) acc2[r][j] = fma2(a2[r], b2v[j], acc2[r][j]);
        }
    }
    __syncthreads();   // all Us (u) reads done before overwriting with y
    #pragma unroll
    for (int r = 0; r < 4; r++)
        #pragma unroll
        for (int j = 0; j < 4; j++) {
            float x0, x1;
            upk2(acc2[r][j], x0, x1);
            int row = ty * 4 + r;
            int col0 = 32 * j + 2 * tx;
            float2 bb = *(const float2*)(b2 + col0);
            float2 ee = *(const float2*)(Es + row * 132 + col0);
            float2 yo;
            yo.x = x0 + bb.x + ee.x;
            yo.y = x1 + bb.y + ee.y;
            *(float2*)(Us + row * 132 + col0) = yo;
        }
    __syncthreads();

    // ---- LayerNorm: 8 warps x 8 rows (verbatim R1) ----
    const int wid = tid >> 5, lane = tid & 31;
    #pragma unroll
    for (int rr = 0; rr < 8; rr++) {
        int row = wid * 8 + rr;
        float v[4];
        #pragma unroll
        for (int q = 0; q < 4; q++) v[q] = Us[row * 132 + lane + 32 * q];
        float s = v[0] + v[1] + v[2] + v[3];
        #pragma unroll
        for (int o = 16; o; o >>= 1) s += __shfl_xor_sync(0xffffffffu, s, o);
        float mu = s * (1.f / 128.f);
        float d[4], sq = 0.f;
        #pragma unroll
        for (int q = 0; q < 4; q++) { d[q] = v[q] - mu; sq = fmaf(d[q], d[q], sq); }
        #pragma unroll
        for (int o = 16; o; o >>= 1) sq += __shfl_xor_sync(0xffffffffu, sq, o);
        float inv = rsqrtf(sq * (1.f / 128.f) + 1e-5f);
        size_t base = (size_t)(tok0 + row) * H_;
        #pragma unroll
        for (int q = 0; q < 4; q++) {
            int col = lane + 32 * q;
            g_h[base + col] = d[q] * inv * gamma[col] + beta[col];
        }
    }
}

// =====================================================================
// Scan v6: same structure as v5 (passed); vp_part stride 20 so the
// phase-2 serial sum loads as 4x LDS.128. Add chain order unchanged
// (same unrolled 16-term serial loop) -> bit-identical.
// =====================================================================
__global__ void __launch_bounds__(256, 2) scan_kernel()
{
    __shared__ float k_s[2][128];
    __shared__ float red_k[2][4];
    __shared__ float err_s[128];
    __shared__ float red_e[4];
    __shared__ __align__(16) float vp_part[128][20];   // tid*80B: 16B-aligned rows

    const int bb   = blockIdx.x;
    const int tid  = threadIdx.x;
    const int ty   = tid >> 4, tx = tid & 15;
    const int lane = tid & 31;
    const float* __restrict__ hb = g_h + (size_t)bb * L_ * H_;

    uint64_t M2[4][8];
    #pragma unroll
    for (int p = 0; p < 4; p++)
        #pragma unroll
        for (int c = 0; c < 8; c++) M2[p][c] = 0ull;

    float kn0 = 0.f, kn1 = 0.f;
    if (tid >= 128) {
        const int i = tid - 128;
        float kv = hb[i];
        k_s[0][i] = kv;
        float p = kv * kv;
        #pragma unroll
        for (int o = 16; o; o >>= 1) p += __shfl_xor_sync(0xffffffffu, p, o);
        if (lane == 0) red_k[0][i >> 5] = p;
        kn0 = hb[128 + i];
        kn1 = hb[256 + i];
    }
    __syncthreads();

    for (int t = 0; t < L_ - 1; t++) {
        const int buf = t & 1;

        float kreg[8];
        uint64_t k2[8];
        {
            float4 kA = *(const float4*)(&k_s[buf][tx * 8]);
            float4 kB = *(const float4*)(&k_s[buf][tx * 8 + 4]);
            kreg[0] = kA.x; kreg[1] = kA.y; kreg[2] = kA.z; kreg[3] = kA.w;
            kreg[4] = kB.x; kreg[5] = kB.y; kreg[6] = kB.z; kreg[7] = kB.w;
        }
        #pragma unroll
        for (int c = 0; c < 8; c++) k2[c] = pk2(kreg[c], kreg[c]);

        #pragma unroll
        for (int p = 0; p < 4; p++) {
            uint64_t s2 = 0ull;
            #pragma unroll
            for (int c = 0; c < 8; c++) s2 = fma2(M2[p][c], k2[c], s2);
            float slo, shi;
            upk2(s2, slo, shi);
            vp_part[ty * 8 + 2 * p][tx]     = slo;
            vp_part[ty * 8 + 2 * p + 1][tx] = shi;
        }
        if (tid >= 128) {
            const int i = tid - 128;
            k_s[buf ^ 1][i] = kn0;
            float p = kn0 * kn0;
            #pragma unroll
            for (int o = 16; o; o >>= 1) p += __shfl_xor_sync(0xffffffffu, p, o);
            if (lane == 0) red_k[buf ^ 1][i >> 5] = p;
            kn0 = kn1;
            kn1 = (t + 3 < L_) ? hb[(size_t)(t + 3) * H_ + i] : 0.f;
        }
        __syncthreads();                          // A

        const float kk = red_k[buf][0] + red_k[buf][1] + red_k[buf][2] + red_k[buf][3];

        if (tid < 128) {
            const float4* vp4 = (const float4*)(&vp_part[tid][0]);
            float4 q0 = vp4[0], q1 = vp4[1], q2 = vp4[2], q3 = vp4[3];
            float v[16] = { q0.x, q0.y, q0.z, q0.w,
                            q1.x, q1.y, q1.z, q1.w,
                            q2.x, q2.y, q2.z, q2.w,
                            q3.x, q3.y, q3.z, q3.w };
            float vp = 0.f;
            #pragma unroll
            for (int x = 0; x < 16; x++) vp += v[x];      // same serial chain as R1
            float e = k_s[buf][tid] - vp / (kk + 1e-6f);
            err_s[tid] = e;
            float p = e * e;
            #pragma unroll
            for (int o = 16; o; o >>= 1) p += __shfl_xor_sync(0xffffffffu, p, o);
            if (lane == 0) red_e[tid >> 5] = p;
        }
        __syncthreads();                          // B

        float e2 = red_e[0] + red_e[1] + red_e[2] + red_e[3];
        if (sqrtf(e2) > 0.4f * sqrtf(kk)) {
            #pragma unroll
            for (int p = 0; p < 4; p++) {
                float2 ep = *(const float2*)(&err_s[ty * 8 + 2 * p]);
                uint64_t er2 = pk2(ep.x, ep.y);
                #pragma unroll
                for (int c = 0; c < 8; c++) M2[p][c] = fma2(er2, k2[c], M2[p][c]);
            }
        }
    }

    {
        const int buf = (L_ - 1) & 1;
        uint64_t k2[8];
        {
            float4 kA = *(const float4*)(&k_s[buf][tx * 8]);
            float4 kB = *(const float4*)(&k_s[buf][tx * 8 + 4]);
            k2[0] = pk2(kA.x, kA.x); k2[1] = pk2(kA.y, kA.y);
            k2[2] = pk2(kA.z, kA.z); k2[3] = pk2(kA.w, kA.w);
            k2[4] = pk2(kB.x, kB.x); k2[5] = pk2(kB.y, kB.y);
            k2[6] = pk2(kB.z, kB.z); k2[7] = pk2(kB.w, kB.w);
        }
        #pragma unroll
        for (int p = 0; p < 4; p++) {
            uint64_t s2 = 0ull;
            #pragma unroll
            for (int c = 0; c < 8; c++) s2 = fma2(M2[p][c], k2[c], s2);
            float slo, shi;
            upk2(s2, slo, shi);
            vp_part[ty * 8 + 2 * p][tx]     = slo;
            vp_part[ty * 8 + 2 * p + 1][tx] = shi;
        }
        __syncthreads();
        if (tid < 128) {
            const float4* vp4 = (const float4*)(&vp_part[tid][0]);
            float4 q0 = vp4[0], q1 = vp4[1], q2 = vp4[2], q3 = vp4[3];
            float v[16] = { q0.x, q0.y, q0.z, q0.w,
                            q1.x, q1.y, q1.z, q1.w,
                            q2.x, q2.y, q2.z, q2.w,
                            q3.x, q3.y, q3.z, q3.w };
            float vp = 0.f;
            #pragma unroll
            for (int x = 0; x < 16; x++) vp += v[x];
            g_r[bb * H_ + tid] = vp;
        }
    }
}

// =====================================================================
// Kernel 3: r2 = r @ Wrp + brp
// =====================================================================
__global__ void __launch_bounds__(256, 1) rproj_kernel(
    const float* __restrict__ Wrp, const float* __restrict__ brp)
{
    extern __shared__ float smf[];
    float* Rs = smf;
    float* Ws = smf + 64 * 132;
    const int tid = threadIdx.x, ty = tid >> 4, tx = tid & 15;
    const int m0 = blockIdx.x * 64;

    for (int i = tid; i < 64 * 128; i += 256) {
        int r = i >> 7, c = i & 127;
        Rs[r * 132 + c] = g_r[(m0 + r) * H_ + c];
    }
    for (int i = tid; i < 128 * 128; i += 256) Ws[i] = Wrp[i];
    __syncthreads();

    float acc[4][8];
    #pragma unroll
    for (int r = 0; r < 4; r++)
        #pragma unroll
        for (int j = 0; j < 8; j++) acc[r][j] = 0.f;
    #pragma unroll 8
    for (int k = 0; k < 128; k++) {
        float a[4], bbv[8];
        #pragma unroll
        for (int r = 0; r < 4; r++) a[r] = Rs[(ty * 4 + r) * 132 + k];
        #pragma unroll
        for (int j = 0; j < 8; j++) bbv[j] = Ws[k * 128 + tx + 16 * j];
        #pragma unroll
        for (int r = 0; r < 4; r++)
            #pragma unroll
            for (int j = 0; j < 8; j++) acc[r][j] = fmaf(a[r], bbv[j], acc[r][j]);
    }
    #pragma unroll
    for (int r = 0; r < 4; r++)
        #pragma unroll
        for (int j = 0; j < 8; j++) {
            int rr = m0 + ty * 4 + r, cc = tx + 16 * j;
            g_r2[rr * H_ + cc] = acc[r][j] + brp[cc];
        }
}

// =====================================================================
// Kernel 4: out = r2 @ Wout + bout
// =====================================================================
__global__ void __launch_bounds__(256, 1) out_kernel(
    const float* __restrict__ Wout, const float* __restrict__ bout,
    float* __restrict__ out)
{
    extern __shared__ float smf[];
    float* Rs = smf;
    float* Ws = smf + 64 * 132;
    const int tid = threadIdx.x, ty = tid >> 4, tx = tid & 15;
    const int n0 = blockIdx.x * 128;
    const int m0 = blockIdx.y * 64;

    for (int i = tid; i < 64 * 128; i += 256) {
        int r = i >> 7, c = i & 127;
        Rs[r * 132 + c] = g_r2[(m0 + r) * H_ + c];
    }
    for (int i = tid; i < 128 * 128; i += 256) {
        int k = i >> 7, c = i & 127;
        Ws[i] = Wout[(size_t)k * V_ + n0 + c];
    }
    __syncthreads();

    float acc[4][8];
    #pragma unroll
    for (int r = 0; r < 4; r++)
        #pragma unroll
        for (int j = 0; j < 8; j++) acc[r][j] = 0.f;
    #pragma unroll 8
    for (int k = 0; k < 128; k++) {
        float a[4], bbv[8];
        #pragma unroll
        for (int r = 0; r < 4; r++) a[r] = Rs[(ty * 4 + r) * 132 + k];
        #pragma unroll
        for (int j = 0; j < 8; j++) bbv[j] = Ws[k * 128 + tx + 16 * j];
        #pragma unroll
        for (int r = 0; r < 4; r++)
            #pragma unroll
            for (int j = 0; j < 8; j++) acc[r][j] = fmaf(a[r], bbv[j], acc[r][j]);
    }
    #pragma unroll
    for (int r = 0; r < 4; r++)
        #pragma unroll
        for (int j = 0; j < 8; j++) {
            int rr = m0 + ty * 4 + r, cc = n0 + tx + 16 * j;
            out[(size_t)rr * V_ + cc] = acc[r][j] + bout[cc];
        }
}

// =====================================================================
// launcher
// =====================================================================
extern "C" void kernel_launch(void* const* d_in, const int* in_sizes, int n_in,
                              void* d_out, int out_size)
{
    const int*   seq   = (const int*)  d_in[0];
    const float* embed = (const float*)d_in[1];
    const float* W1    = (const float*)d_in[2];
    const float* b1    = (const float*)d_in[3];
    const float* W2    = (const float*)d_in[4];
    const float* b2    = (const float*)d_in[5];
    const float* gamma = (const float*)d_in[6];
    const float* beta  = (const float*)d_in[7];
    const float* Wrp   = (const float*)d_in[8];
    const float* brp   = (const float*)d_in[9];
    const float* Wout  = (const float*)d_in[10];
    const float* bout  = (const float*)d_in[11];
    float* out = (float*)d_out;

    const int PROJ_SMEM = (64 * 132 + 128 * 128) * 4;

    cudaFuncSetAttribute(encode_ffma2, cudaFuncAttributeMaxDynamicSharedMemorySize, ENC_SMEM);
    cudaFuncSetAttribute(rproj_kernel, cudaFuncAttributeMaxDynamicSharedMemorySize, PROJ_SMEM);
    cudaFuncSetAttribute(out_kernel,   cudaFuncAttributeMaxDynamicSharedMemorySize, PROJ_SMEM);

    // profiling alignment: keep ncu's -s 5 window on encode_ffma2
    dummy_kernel<<<1, 32>>>();
    dummy_kernel<<<1, 32>>>();
    dummy_kernel<<<1, 32>>>();

    encode_ffma2<<<(B_ * L_) / TB, 256, ENC_SMEM>>>(seq, embed, W1, b1, W2, b2, gamma, beta);
    scan_kernel<<<B_, 256>>>();
    rproj_kernel<<<B_ / 64, 256, PROJ_SMEM>>>(Wrp, brp);
    out_kernel<<<dim3(V_ / 128, B_ / 64), 256, PROJ_SMEM>>>(Wout, bout, out);
}

// round 14
// speedup vs baseline: 1.0154x; 1.0154x over previous
#include <cuda_runtime.h>
#include <cstdint>
#include <cstddef>

#define B_  256
#define L_  2048
#define H_  128
#define H2_ 256
#define V_  32000
#define TB  64        // tokens per encode block

// ---------------- scratch (static device globals; no allocs allowed) ----------------
__device__ float g_h[(size_t)B_ * L_ * H_];   // encoded h_all [B,L,H]
__device__ float g_r[B_ * H_];
__device__ float g_r2[B_ * H_];

// ============ packed f32x2 helpers (FFMA2 — Blackwell, PTX-only path) ============
__device__ __forceinline__ uint64_t pk2(float lo, float hi) {
    uint64_t r;
    asm("mov.b64 %0, {%1, %2};" : "=l"(r) : "f"(lo), "f"(hi));
    return r;
}
__device__ __forceinline__ void upk2(uint64_t v, float& lo, float& hi) {
    asm("mov.b64 {%0, %1}, %2;" : "=f"(lo), "=f"(hi) : "l"(v));
}
__device__ __forceinline__ uint64_t fma2(uint64_t a, uint64_t b, uint64_t c) {
    uint64_t d;
    asm("fma.rn.f32x2 %0, %1, %2, %3;" : "=l"(d) : "l"(a), "l"(b), "l"(c));
    return d;
}

// ---------------- profiling-alignment dummies ----------------
__global__ void dummy_kernel() {}

// =====================================================================
// Encode (FFMA2, LDS.128 b-operands, k-paired a-loads).
// Column re-pairing & load merging don't alter any per-column
// accumulation chain -> bit-identical to R1. 64 tokens/CTA, 256 thr.
// Thread (ty,tx): rows ty*4+r, cols 64j + 4tx + {0..3}.
// =====================================================================
#define ENC_SMEM ((64 * 132 + 64 * 260 + 32 * 256) * 4)   // 133120 B

__global__ void __launch_bounds__(256, 1) encode_ffma2(
    const int*   __restrict__ seq,   const float* __restrict__ embed,
    const float* __restrict__ W1,    const float* __restrict__ b1,
    const float* __restrict__ W2,    const float* __restrict__ b2,
    const float* __restrict__ gamma, const float* __restrict__ beta)
{
    extern __shared__ float sm[];
    float* Es = sm;               // [64][132]
    float* Us = Es + 64 * 132;    // [64][260] (u), reused as y [64][132]
    float* Ws = Us + 64 * 260;    // weight chunk, up to [32][256]

    const int tid = threadIdx.x;
    const int ty  = tid >> 4;     // 0..15
    const int tx  = tid & 15;     // 0..15
    const int tok0 = blockIdx.x * TB;

    // ---- gather embeddings (float4) ----
    for (int i = tid; i < TB * 32; i += 256) {
        int row = i >> 5, q = i & 31;
        int s = seq[tok0 + row];
        float4 v = *(const float4*)(embed + (size_t)s * H_ + 4 * q);
        *(float4*)(Es + row * 132 + 4 * q) = v;
    }

    // ---- GEMM1: u = relu(e @ W1 + b1)  (64x256, K=128) ----
    // acc[r][j][h]: rows ty*4+r, cols 64j+4tx+2h+{0,1}
    uint64_t acc[4][4][2];
    #pragma unroll
    for (int r = 0; r < 4; r++)
        #pragma unroll
        for (int j = 0; j < 4; j++) { acc[r][j][0] = 0ull; acc[r][j][1] = 0ull; }

    for (int kc = 0; kc < H_; kc += 32) {
        __syncthreads();
        {   // contiguous 32KB copy: W1 rows kc..kc+31 (float4)
            const float4* src = (const float4*)(W1 + kc * H2_);
            float4* dst = (float4*)Ws;
            for (int i = tid; i < 2048; i += 256) dst[i] = src[i];
        }
        __syncthreads();
        #pragma unroll 4
        for (int kp = 0; kp < 16; kp++) {          // k-pairs
            float2 av[4];
            #pragma unroll
            for (int r = 0; r < 4; r++)
                av[r] = *(const float2*)(Es + (ty * 4 + r) * 132 + kc + 2 * kp);
            #pragma unroll
            for (int s = 0; s < 2; s++) {
                const int kk = 2 * kp + s;
                uint64_t a2[4];
                #pragma unroll
                for (int r = 0; r < 4; r++) {
                    float a = s ? av[r].y : av[r].x;
                    a2[r] = pk2(a, a);
                }
                #pragma unroll
                for (int j = 0; j < 4; j++) {
                    float4 bw = *(const float4*)(Ws + kk * H2_ + 64 * j + 4 * tx);
                    uint64_t b0 = pk2(bw.x, bw.y);
                    uint64_t b1v = pk2(bw.z, bw.w);
                    #pragma unroll
                    for (int r = 0; r < 4; r++) {
                        acc[r][j][0] = fma2(a2[r], b0,  acc[r][j][0]);
                        acc[r][j][1] = fma2(a2[r], b1v, acc[r][j][1]);
                    }
                }
            }
        }
    }
    __syncthreads();
    #pragma unroll
    for (int r = 0; r < 4; r++)
        #pragma unroll
        for (int j = 0; j < 4; j++) {
            float x0, x1, x2, x3;
            upk2(acc[r][j][0], x0, x1);
            upk2(acc[r][j][1], x2, x3);
            int col0 = 64 * j + 4 * tx;
            float4 bb = *(const float4*)(b1 + col0);
            float4 uo;
            uo.x = fmaxf(x0 + bb.x, 0.f);
            uo.y = fmaxf(x1 + bb.y, 0.f);
            uo.z = fmaxf(x2 + bb.z, 0.f);
            uo.w = fmaxf(x3 + bb.w, 0.f);
            *(float4*)(Us + (ty * 4 + r) * 260 + col0) = uo;
        }

    // ---- GEMM2: y = u @ W2 + b2 + e  (64x128, K=256) ----
    uint64_t acc2[4][2][2];
    #pragma unroll
    for (int r = 0; r < 4; r++)
        #pragma unroll
        for (int j = 0; j < 2; j++) { acc2[r][j][0] = 0ull; acc2[r][j][1] = 0ull; }

    for (int kc = 0; kc < H2_; kc += 32) {
        __syncthreads();
        {   // contiguous 16KB copy: W2 rows kc..kc+31 (float4)
            const float4* src = (const float4*)(W2 + kc * H_);
            float4* dst = (float4*)Ws;
            for (int i = tid; i < 1024; i += 256) dst[i] = src[i];
        }
        __syncthreads();
        #pragma unroll 4
        for (int kp = 0; kp < 16; kp++) {
            float2 av[4];
            #pragma unroll
            for (int r = 0; r < 4; r++)
                av[r] = *(const float2*)(Us + (ty * 4 + r) * 260 + kc + 2 * kp);
            #pragma unroll
            for (int s = 0; s < 2; s++) {
                const int kk = 2 * kp + s;
                uint64_t a2[4];
                #pragma unroll
                for (int r = 0; r < 4; r++) {
                    float a = s ? av[r].y : av[r].x;
                    a2[r] = pk2(a, a);
                }
                #pragma unroll
                for (int j = 0; j < 2; j++) {
                    float4 bw = *(const float4*)(Ws + kk * H_ + 64 * j + 4 * tx);
                    uint64_t b0 = pk2(bw.x, bw.y);
                    uint64_t b1v = pk2(bw.z, bw.w);
                    #pragma unroll
                    for (int r = 0; r < 4; r++) {
                        acc2[r][j][0] = fma2(a2[r], b0,  acc2[r][j][0]);
                        acc2[r][j][1] = fma2(a2[r], b1v, acc2[r][j][1]);
                    }
                }
            }
        }
    }
    __syncthreads();   // all Us (u) reads done before overwriting with y
    #pragma unroll
    for (int r = 0; r < 4; r++)
        #pragma unroll
        for (int j = 0; j < 2; j++) {
            float x0, x1, x2, x3;
            upk2(acc2[r][j][0], x0, x1);
            upk2(acc2[r][j][1], x2, x3);
            int row = ty * 4 + r;
            int col0 = 64 * j + 4 * tx;
            float4 bb = *(const float4*)(b2 + col0);
            float4 ee = *(const float4*)(Es + row * 132 + col0);
            float4 yo;
            yo.x = x0 + bb.x + ee.x;
            yo.y = x1 + bb.y + ee.y;
            yo.z = x2 + bb.z + ee.z;
            yo.w = x3 + bb.w + ee.w;
            *(float4*)(Us + row * 132 + col0) = yo;
        }
    __syncthreads();

    // ---- LayerNorm: 8 warps x 8 rows (verbatim R1) ----
    const int wid = tid >> 5, lane = tid & 31;
    #pragma unroll
    for (int rr = 0; rr < 8; rr++) {
        int row = wid * 8 + rr;
        float v[4];
        #pragma unroll
        for (int q = 0; q < 4; q++) v[q] = Us[row * 132 + lane + 32 * q];
        float s = v[0] + v[1] + v[2] + v[3];
        #pragma unroll
        for (int o = 16; o; o >>= 1) s += __shfl_xor_sync(0xffffffffu, s, o);
        float mu = s * (1.f / 128.f);
        float d[4], sq = 0.f;
        #pragma unroll
        for (int q = 0; q < 4; q++) { d[q] = v[q] - mu; sq = fmaf(d[q], d[q], sq); }
        #pragma unroll
        for (int o = 16; o; o >>= 1) sq += __shfl_xor_sync(0xffffffffu, sq, o);
        float inv = rsqrtf(sq * (1.f / 128.f) + 1e-5f);
        size_t base = (size_t)(tok0 + row) * H_;
        #pragma unroll
        for (int q = 0; q < 4; q++) {
            int col = lane + 32 * q;
            g_h[base + col] = d[q] * inv * gamma[col] + beta[col];
        }
    }
}

// =====================================================================
// Scan v5 (R10 verbatim — best passing version)
// =====================================================================
__global__ void __launch_bounds__(256, 2) scan_kernel()
{
    __shared__ float k_s[2][128];
    __shared__ float red_k[2][4];
    __shared__ float err_s[128];
    __shared__ float red_e[4];
    __shared__ float vp_part[128][17];

    const int bb   = blockIdx.x;
    const int tid  = threadIdx.x;
    const int ty   = tid >> 4, tx = tid & 15;
    const int lane = tid & 31;
    const float* __restrict__ hb = g_h + (size_t)bb * L_ * H_;

    uint64_t M2[4][8];
    #pragma unroll
    for (int p = 0; p < 4; p++)
        #pragma unroll
        for (int c = 0; c < 8; c++) M2[p][c] = 0ull;

    float kn0 = 0.f, kn1 = 0.f;
    if (tid >= 128) {
        const int i = tid - 128;
        float kv = hb[i];
        k_s[0][i] = kv;
        float p = kv * kv;
        #pragma unroll
        for (int o = 16; o; o >>= 1) p += __shfl_xor_sync(0xffffffffu, p, o);
        if (lane == 0) red_k[0][i >> 5] = p;
        kn0 = hb[128 + i];
        kn1 = hb[256 + i];
    }
    __syncthreads();

    for (int t = 0; t < L_ - 1; t++) {
        const int buf = t & 1;

        float kreg[8];
        uint64_t k2[8];
        {
            float4 kA = *(const float4*)(&k_s[buf][tx * 8]);
            float4 kB = *(const float4*)(&k_s[buf][tx * 8 + 4]);
            kreg[0] = kA.x; kreg[1] = kA.y; kreg[2] = kA.z; kreg[3] = kA.w;
            kreg[4] = kB.x; kreg[5] = kB.y; kreg[6] = kB.z; kreg[7] = kB.w;
        }
        #pragma unroll
        for (int c = 0; c < 8; c++) k2[c] = pk2(kreg[c], kreg[c]);

        #pragma unroll
        for (int p = 0; p < 4; p++) {
            uint64_t s2 = 0ull;
            #pragma unroll
            for (int c = 0; c < 8; c++) s2 = fma2(M2[p][c], k2[c], s2);
            float slo, shi;
            upk2(s2, slo, shi);
            vp_part[ty * 8 + 2 * p][tx]     = slo;
            vp_part[ty * 8 + 2 * p + 1][tx] = shi;
        }
        if (tid >= 128) {
            const int i = tid - 128;
            k_s[buf ^ 1][i] = kn0;
            float p = kn0 * kn0;
            #pragma unroll
            for (int o = 16; o; o >>= 1) p += __shfl_xor_sync(0xffffffffu, p, o);
            if (lane == 0) red_k[buf ^ 1][i >> 5] = p;
            kn0 = kn1;
            kn1 = (t + 3 < L_) ? hb[(size_t)(t + 3) * H_ + i] : 0.f;
        }
        __syncthreads();                          // A

        const float kk = red_k[buf][0] + red_k[buf][1] + red_k[buf][2] + red_k[buf][3];

        if (tid < 128) {
            float vp = 0.f;
            #pragma unroll
            for (int x = 0; x < 16; x++) vp += vp_part[tid][x];
            float e = k_s[buf][tid] - vp / (kk + 1e-6f);
            err_s[tid] = e;
            float p = e * e;
            #pragma unroll
            for (int o = 16; o; o >>= 1) p += __shfl_xor_sync(0xffffffffu, p, o);
            if (lane == 0) red_e[tid >> 5] = p;
        }
        __syncthreads();                          // B

        float e2 = red_e[0] + red_e[1] + red_e[2] + red_e[3];
        if (sqrtf(e2) > 0.4f * sqrtf(kk)) {
            #pragma unroll
            for (int p = 0; p < 4; p++) {
                float2 ep = *(const float2*)(&err_s[ty * 8 + 2 * p]);
                uint64_t er2 = pk2(ep.x, ep.y);
                #pragma unroll
                for (int c = 0; c < 8; c++) M2[p][c] = fma2(er2, k2[c], M2[p][c]);
            }
        }
    }

    {
        const int buf = (L_ - 1) & 1;
        uint64_t k2[8];
        {
            float4 kA = *(const float4*)(&k_s[buf][tx * 8]);
            float4 kB = *(const float4*)(&k_s[buf][tx * 8 + 4]);
            k2[0] = pk2(kA.x, kA.x); k2[1] = pk2(kA.y, kA.y);
            k2[2] = pk2(kA.z, kA.z); k2[3] = pk2(kA.w, kA.w);
            k2[4] = pk2(kB.x, kB.x); k2[5] = pk2(kB.y, kB.y);
            k2[6] = pk2(kB.z, kB.z); k2[7] = pk2(kB.w, kB.w);
        }
        #pragma unroll
        for (int p = 0; p < 4; p++) {
            uint64_t s2 = 0ull;
            #pragma unroll
            for (int c = 0; c < 8; c++) s2 = fma2(M2[p][c], k2[c], s2);
            float slo, shi;
            upk2(s2, slo, shi);
            vp_part[ty * 8 + 2 * p][tx]     = slo;
            vp_part[ty * 8 + 2 * p + 1][tx] = shi;
        }
        __syncthreads();
        if (tid < 128) {
            float vp = 0.f;
            #pragma unroll
            for (int x = 0; x < 16; x++) vp += vp_part[tid][x];
            g_r[bb * H_ + tid] = vp;
        }
    }
}

// =====================================================================
// Kernel 3: r2 = r @ Wrp + brp
// =====================================================================
__global__ void __launch_bounds__(256, 1) rproj_kernel(
    const float* __restrict__ Wrp, const float* __restrict__ brp)
{
    extern __shared__ float smf[];
    float* Rs = smf;
    float* Ws = smf + 64 * 132;
    const int tid = threadIdx.x, ty = tid >> 4, tx = tid & 15;
    const int m0 = blockIdx.x * 64;

    for (int i = tid; i < 64 * 128; i += 256) {
        int r = i >> 7, c = i & 127;
        Rs[r * 132 + c] = g_r[(m0 + r) * H_ + c];
    }
    for (int i = tid; i < 128 * 128; i += 256) Ws[i] = Wrp[i];
    __syncthreads();

    float acc[4][8];
    #pragma unroll
    for (int r = 0; r < 4; r++)
        #pragma unroll
        for (int j = 0; j < 8; j++) acc[r][j] = 0.f;
    #pragma unroll 8
    for (int k = 0; k < 128; k++) {
        float a[4], bbv[8];
        #pragma unroll
        for (int r = 0; r < 4; r++) a[r] = Rs[(ty * 4 + r) * 132 + k];
        #pragma unroll
        for (int j = 0; j < 8; j++) bbv[j] = Ws[k * 128 + tx + 16 * j];
        #pragma unroll
        for (int r = 0; r < 4; r++)
            #pragma unroll
            for (int j = 0; j < 8; j++) acc[r][j] = fmaf(a[r], bbv[j], acc[r][j]);
    }
    #pragma unroll
    for (int r = 0; r < 4; r++)
        #pragma unroll
        for (int j = 0; j < 8; j++) {
            int rr = m0 + ty * 4 + r, cc = tx + 16 * j;
            g_r2[rr * H_ + cc] = acc[r][j] + brp[cc];
        }
}

// =====================================================================
// Kernel 4: out = r2 @ Wout + bout
// =====================================================================
__global__ void __launch_bounds__(256, 1) out_kernel(
    const float* __restrict__ Wout, const float* __restrict__ bout,
    float* __restrict__ out)
{
    extern __shared__ float smf[];
    float* Rs = smf;
    float* Ws = smf + 64 * 132;
    const int tid = threadIdx.x, ty = tid >> 4, tx = tid & 15;
    const int n0 = blockIdx.x * 128;
    const int m0 = blockIdx.y * 64;

    for (int i = tid; i < 64 * 128; i += 256) {
        int r = i >> 7, c = i & 127;
        Rs[r * 132 + c] = g_r2[(m0 + r) * H_ + c];
    }
    for (int i = tid; i < 128 * 128; i += 256) {
        int k = i >> 7, c = i & 127;
        Ws[i] = Wout[(size_t)k * V_ + n0 + c];
    }
    __syncthreads();

    float acc[4][8];
    #pragma unroll
    for (int r = 0; r < 4; r++)
        #pragma unroll
        for (int j = 0; j < 8; j++) acc[r][j] = 0.f;
    #pragma unroll 8
    for (int k = 0; k < 128; k++) {
        float a[4], bbv[8];
        #pragma unroll
        for (int r = 0; r < 4; r++) a[r] = Rs[(ty * 4 + r) * 132 + k];
        #pragma unroll
        for (int j = 0; j < 8; j++) bbv[j] = Ws[k * 128 + tx + 16 * j];
        #pragma unroll
        for (int r = 0; r < 4; r++)
            #pragma unroll
            for (int j = 0; j < 8; j++) acc[r][j] = fmaf(a[r], bbv[j], acc[r][j]);
    }
    #pragma unroll
    for (int r = 0; r < 4; r++)
        #pragma unroll
        for (int j = 0; j < 8; j++) {
            int rr = m0 + ty * 4 + r, cc = n0 + tx + 16 * j;
            out[(size_t)rr * V_ + cc] = acc[r][j] + bout[cc];
        }
}

// =====================================================================
// launcher
// =====================================================================
extern "C" void kernel_launch(void* const* d_in, const int* in_sizes, int n_in,
                              void* d_out, int out_size)
{
    const int*   seq   = (const int*)  d_in[0];
    const float* embed = (const float*)d_in[1];
    const float* W1    = (const float*)d_in[2];
    const float* b1    = (const float*)d_in[3];
    const float* W2    = (const float*)d_in[4];
    const float* b2    = (const float*)d_in[5];
    const float* gamma = (const float*)d_in[6];
    const float* beta  = (const float*)d_in[7];
    const float* Wrp   = (const float*)d_in[8];
    const float* brp   = (const float*)d_in[9];
    const float* Wout  = (const float*)d_in[10];
    const float* bout  = (const float*)d_in[11];
    float* out = (float*)d_out;

    const int PROJ_SMEM = (64 * 132 + 128 * 128) * 4;

    cudaFuncSetAttribute(encode_ffma2, cudaFuncAttributeMaxDynamicSharedMemorySize, ENC_SMEM);
    cudaFuncSetAttribute(rproj_kernel, cudaFuncAttributeMaxDynamicSharedMemorySize, PROJ_SMEM);
    cudaFuncSetAttribute(out_kernel,   cudaFuncAttributeMaxDynamicSharedMemorySize, PROJ_SMEM);

    // profiling alignment: keep ncu's -s 5 window on encode_ffma2
    dummy_kernel<<<1, 32>>>();
    dummy_kernel<<<1, 32>>>();
    dummy_kernel<<<1, 32>>>();

    encode_ffma2<<<(B_ * L_) / TB, 256, ENC_SMEM>>>(seq, embed, W1, b1, W2, b2, gamma, beta);
    scan_kernel<<<B_, 256>>>();
    rproj_kernel<<<B_ / 64, 256, PROJ_SMEM>>>(Wrp, brp);
    out_kernel<<<dim3(V_ / 128, B_ / 64), 256, PROJ_SMEM>>>(Wout, bout, out);
}

// round 15
// speedup vs baseline: 1.1504x; 1.1330x over previous
#include <cuda_runtime.h>
#include <cstdint>
#include <cstddef>

#define B_  256
#define L_  2048
#define H_  128
#define H2_ 256
#define V_  32000
#define TB  64        // tokens per encode block

// ---------------- scratch (static device globals; no allocs allowed) ----------------
__device__ float g_h[(size_t)B_ * L_ * H_];   // encoded h_all [B,L,H]
__device__ float g_r[B_ * H_];
__device__ float g_r2[B_ * H_];

// ============ packed f32x2 helpers (FFMA2 — Blackwell, PTX-only path) ============
__device__ __forceinline__ uint64_t pk2(float lo, float hi) {
    uint64_t r;
    asm("mov.b64 %0, {%1, %2};" : "=l"(r) : "f"(lo), "f"(hi));
    return r;
}
__device__ __forceinline__ void upk2(uint64_t v, float& lo, float& hi) {
    asm("mov.b64 {%0, %1}, %2;" : "=f"(lo), "=f"(hi) : "l"(v));
}
__device__ __forceinline__ uint64_t fma2(uint64_t a, uint64_t b, uint64_t c) {
    uint64_t d;
    asm("fma.rn.f32x2 %0, %1, %2, %3;" : "=l"(d) : "l"(a), "l"(b), "l"(c));
    return d;
}

// ---------------- profiling-alignment dummies ----------------
__global__ void dummy_kernel() {}

// =====================================================================
// Encode (FFMA2, LDS.128 b-operands, 2 CTAs/SM).
// smem 112 KB: EPAD=128, UPAD=256, 16-row weight chunks.
// All accumulation chains identical to R1 -> bit-identical output.
// Thread (ty,tx): rows ty*4+r, cols 64j + 4tx + {0..3}.
// =====================================================================
#define EPAD 128
#define UPAD 256
#define ENC_SMEM ((64 * EPAD + 64 * UPAD + 16 * 256) * 4)   // 114688 B

__global__ void __launch_bounds__(256, 2) encode_ffma2(
    const int*   __restrict__ seq,   const float* __restrict__ embed,
    const float* __restrict__ W1,    const float* __restrict__ b1,
    const float* __restrict__ W2,    const float* __restrict__ b2,
    const float* __restrict__ gamma, const float* __restrict__ beta)
{
    extern __shared__ float sm[];
    float* Es = sm;                   // [64][128]
    float* Us = Es + 64 * EPAD;       // [64][256] (u), reused as y [64][132]... y stride 132 fits
    float* Ws = Us + 64 * UPAD;       // weight chunk, 16 rows

    const int tid = threadIdx.x;
    const int ty  = tid >> 4;     // 0..15
    const int tx  = tid & 15;     // 0..15
    const int tok0 = blockIdx.x * TB;

    // ---- gather embeddings (float4) ----
    for (int i = tid; i < TB * 32; i += 256) {
        int row = i >> 5, q = i & 31;
        int s = seq[tok0 + row];
        float4 v = *(const float4*)(embed + (size_t)s * H_ + 4 * q);
        *(float4*)(Es + row * EPAD + 4 * q) = v;
    }

    // ---- GEMM1: u = relu(e @ W1 + b1)  (64x256, K=128), chunks of 16 ----
    uint64_t acc[4][4][2];
    #pragma unroll
    for (int r = 0; r < 4; r++)
        #pragma unroll
        for (int j = 0; j < 4; j++) { acc[r][j][0] = 0ull; acc[r][j][1] = 0ull; }

    for (int kc = 0; kc < H_; kc += 16) {
        __syncthreads();
        {   // contiguous 16KB copy: W1 rows kc..kc+15 (float4)
            const float4* src = (const float4*)(W1 + kc * H2_);
            float4* dst = (float4*)Ws;
            for (int i = tid; i < 1024; i += 256) dst[i] = src[i];
        }
        __syncthreads();
        #pragma unroll 4
        for (int kp = 0; kp < 8; kp++) {           // k-pairs within chunk
            float2 av[4];
            #pragma unroll
            for (int r = 0; r < 4; r++)
                av[r] = *(const float2*)(Es + (ty * 4 + r) * EPAD + kc + 2 * kp);
            #pragma unroll
            for (int s = 0; s < 2; s++) {
                const int kk = 2 * kp + s;
                uint64_t a2[4];
                #pragma unroll
                for (int r = 0; r < 4; r++) {
                    float a = s ? av[r].y : av[r].x;
                    a2[r] = pk2(a, a);
                }
                #pragma unroll
                for (int j = 0; j < 4; j++) {
                    float4 bw = *(const float4*)(Ws + kk * H2_ + 64 * j + 4 * tx);
                    uint64_t b0 = pk2(bw.x, bw.y);
                    uint64_t b1v = pk2(bw.z, bw.w);
                    #pragma unroll
                    for (int r = 0; r < 4; r++) {
                        acc[r][j][0] = fma2(a2[r], b0,  acc[r][j][0]);
                        acc[r][j][1] = fma2(a2[r], b1v, acc[r][j][1]);
                    }
                }
            }
        }
    }
    __syncthreads();
    #pragma unroll
    for (int r = 0; r < 4; r++)
        #pragma unroll
        for (int j = 0; j < 4; j++) {
            float x0, x1, x2, x3;
            upk2(acc[r][j][0], x0, x1);
            upk2(acc[r][j][1], x2, x3);
            int col0 = 64 * j + 4 * tx;
            float4 bb = *(const float4*)(b1 + col0);
            float4 uo;
            uo.x = fmaxf(x0 + bb.x, 0.f);
            uo.y = fmaxf(x1 + bb.y, 0.f);
            uo.z = fmaxf(x2 + bb.z, 0.f);
            uo.w = fmaxf(x3 + bb.w, 0.f);
            *(float4*)(Us + (ty * 4 + r) * UPAD + col0) = uo;
        }

    // ---- GEMM2: y = u @ W2 + b2 + e  (64x128, K=256), chunks of 16 ----
    uint64_t acc2[4][2][2];
    #pragma unroll
    for (int r = 0; r < 4; r++)
        #pragma unroll
        for (int j = 0; j < 2; j++) { acc2[r][j][0] = 0ull; acc2[r][j][1] = 0ull; }

    for (int kc = 0; kc < H2_; kc += 16) {
        __syncthreads();
        {   // contiguous 8KB copy: W2 rows kc..kc+15 (float4)
            const float4* src = (const float4*)(W2 + kc * H_);
            float4* dst = (float4*)Ws;
            for (int i = tid; i < 512; i += 256) dst[i] = src[i];
        }
        __syncthreads();
        #pragma unroll 4
        for (int kp = 0; kp < 8; kp++) {
            float2 av[4];
            #pragma unroll
            for (int r = 0; r < 4; r++)
                av[r] = *(const float2*)(Us + (ty * 4 + r) * UPAD + kc + 2 * kp);
            #pragma unroll
            for (int s = 0; s < 2; s++) {
                const int kk = 2 * kp + s;
                uint64_t a2[4];
                #pragma unroll
                for (int r = 0; r < 4; r++) {
                    float a = s ? av[r].y : av[r].x;
                    a2[r] = pk2(a, a);
                }
                #pragma unroll
                for (int j = 0; j < 2; j++) {
                    float4 bw = *(const float4*)(Ws + kk * H_ + 64 * j + 4 * tx);
                    uint64_t b0 = pk2(bw.x, bw.y);
                    uint64_t b1v = pk2(bw.z, bw.w);
                    #pragma unroll
                    for (int r = 0; r < 4; r++) {
                        acc2[r][j][0] = fma2(a2[r], b0,  acc2[r][j][0]);
                        acc2[r][j][1] = fma2(a2[r], b1v, acc2[r][j][1]);
                    }
                }
            }
        }
    }
    __syncthreads();   // all Us (u) reads done before overwriting with y
    #pragma unroll
    for (int r = 0; r < 4; r++)
        #pragma unroll
        for (int j = 0; j < 2; j++) {
            float x0, x1, x2, x3;
            upk2(acc2[r][j][0], x0, x1);
            upk2(acc2[r][j][1], x2, x3);
            int row = ty * 4 + r;
            int col0 = 64 * j + 4 * tx;
            float4 bb = *(const float4*)(b2 + col0);
            float4 ee = *(const float4*)(Es + row * EPAD + col0);
            float4 yo;
            yo.x = x0 + bb.x + ee.x;
            yo.y = x1 + bb.y + ee.y;
            yo.z = x2 + bb.z + ee.z;
            yo.w = x3 + bb.w + ee.w;
            *(float4*)(Us + row * 132 + col0) = yo;   // y at stride 132 (R1 layout)
        }
    __syncthreads();

    // ---- LayerNorm: 8 warps x 8 rows (verbatim R1; y at stride 132) ----
    const int wid = tid >> 5, lane = tid & 31;
    #pragma unroll
    for (int rr = 0; rr < 8; rr++) {
        int row = wid * 8 + rr;
        float v[4];
        #pragma unroll
        for (int q = 0; q < 4; q++) v[q] = Us[row * 132 + lane + 32 * q];
        float s = v[0] + v[1] + v[2] + v[3];
        #pragma unroll
        for (int o = 16; o; o >>= 1) s += __shfl_xor_sync(0xffffffffu, s, o);
        float mu = s * (1.f / 128.f);
        float d[4], sq = 0.f;
        #pragma unroll
        for (int q = 0; q < 4; q++) { d[q] = v[q] - mu; sq = fmaf(d[q], d[q], sq); }
        #pragma unroll
        for (int o = 16; o; o >>= 1) sq += __shfl_xor_sync(0xffffffffu, sq, o);
        float inv = rsqrtf(sq * (1.f / 128.f) + 1e-5f);
        size_t base = (size_t)(tok0 + row) * H_;
        #pragma unroll
        for (int q = 0; q < 4; q++) {
            int col = lane + 32 * q;
            g_h[base + col] = d[q] * inv * gamma[col] + beta[col];
        }
    }
}

// =====================================================================
// Scan v5 (R10 verbatim — best passing version)
// =====================================================================
__global__ void __launch_bounds__(256, 2) scan_kernel()
{
    __shared__ float k_s[2][128];
    __shared__ float red_k[2][4];
    __shared__ float err_s[128];
    __shared__ float red_e[4];
    __shared__ float vp_part[128][17];

    const int bb   = blockIdx.x;
    const int tid  = threadIdx.x;
    const int ty   = tid >> 4, tx = tid & 15;
    const int lane = tid & 31;
    const float* __restrict__ hb = g_h + (size_t)bb * L_ * H_;

    uint64_t M2[4][8];
    #pragma unroll
    for (int p = 0; p < 4; p++)
        #pragma unroll
        for (int c = 0; c < 8; c++) M2[p][c] = 0ull;

    float kn0 = 0.f, kn1 = 0.f;
    if (tid >= 128) {
        const int i = tid - 128;
        float kv = hb[i];
        k_s[0][i] = kv;
        float p = kv * kv;
        #pragma unroll
        for (int o = 16; o; o >>= 1) p += __shfl_xor_sync(0xffffffffu, p, o);
        if (lane == 0) red_k[0][i >> 5] = p;
        kn0 = hb[128 + i];
        kn1 = hb[256 + i];
    }
    __syncthreads();

    for (int t = 0; t < L_ - 1; t++) {
        const int buf = t & 1;

        float kreg[8];
        uint64_t k2[8];
        {
            float4 kA = *(const float4*)(&k_s[buf][tx * 8]);
            float4 kB = *(const float4*)(&k_s[buf][tx * 8 + 4]);
            kreg[0] = kA.x; kreg[1] = kA.y; kreg[2] = kA.z; kreg[3] = kA.w;
            kreg[4] = kB.x; kreg[5] = kB.y; kreg[6] = kB.z; kreg[7] = kB.w;
        }
        #pragma unroll
        for (int c = 0; c < 8; c++) k2[c] = pk2(kreg[c], kreg[c]);

        #pragma unroll
        for (int p = 0; p < 4; p++) {
            uint64_t s2 = 0ull;
            #pragma unroll
            for (int c = 0; c < 8; c++) s2 = fma2(M2[p][c], k2[c], s2);
            float slo, shi;
            upk2(s2, slo, shi);
            vp_part[ty * 8 + 2 * p][tx]     = slo;
            vp_part[ty * 8 + 2 * p + 1][tx] = shi;
        }
        if (tid >= 128) {
            const int i = tid - 128;
            k_s[buf ^ 1][i] = kn0;
            float p = kn0 * kn0;
            #pragma unroll
            for (int o = 16; o; o >>= 1) p += __shfl_xor_sync(0xffffffffu, p, o);
            if (lane == 0) red_k[buf ^ 1][i >> 5] = p;
            kn0 = kn1;
            kn1 = (t + 3 < L_) ? hb[(size_t)(t + 3) * H_ + i] : 0.f;
        }
        __syncthreads();                          // A

        const float kk = red_k[buf][0] + red_k[buf][1] + red_k[buf][2] + red_k[buf][3];

        if (tid < 128) {
            float vp = 0.f;
            #pragma unroll
            for (int x = 0; x < 16; x++) vp += vp_part[tid][x];
            float e = k_s[buf][tid] - vp / (kk + 1e-6f);
            err_s[tid] = e;
            float p = e * e;
            #pragma unroll
            for (int o = 16; o; o >>= 1) p += __shfl_xor_sync(0xffffffffu, p, o);
            if (lane == 0) red_e[tid >> 5] = p;
        }
        __syncthreads();                          // B

        float e2 = red_e[0] + red_e[1] + red_e[2] + red_e[3];
        if (sqrtf(e2) > 0.4f * sqrtf(kk)) {
            #pragma unroll
            for (int p = 0; p < 4; p++) {
                float2 ep = *(const float2*)(&err_s[ty * 8 + 2 * p]);
                uint64_t er2 = pk2(ep.x, ep.y);
                #pragma unroll
                for (int c = 0; c < 8; c++) M2[p][c] = fma2(er2, k2[c], M2[p][c]);
            }
        }
    }

    {
        const int buf = (L_ - 1) & 1;
        uint64_t k2[8];
        {
            float4 kA = *(const float4*)(&k_s[buf][tx * 8]);
            float4 kB = *(const float4*)(&k_s[buf][tx * 8 + 4]);
            k2[0] = pk2(kA.x, kA.x); k2[1] = pk2(kA.y, kA.y);
            k2[2] = pk2(kA.z, kA.z); k2[3] = pk2(kA.w, kA.w);
            k2[4] = pk2(kB.x, kB.x); k2[5] = pk2(kB.y, kB.y);
            k2[6] = pk2(kB.z, kB.z); k2[7] = pk2(kB.w, kB.w);
        }
        #pragma unroll
        for (int p = 0; p < 4; p++) {
            uint64_t s2 = 0ull;
            #pragma unroll
            for (int c = 0; c < 8; c++) s2 = fma2(M2[p][c], k2[c], s2);
            float slo, shi;
            upk2(s2, slo, shi);
            vp_part[ty * 8 + 2 * p][tx]     = slo;
            vp_part[ty * 8 + 2 * p + 1][tx] = shi;
        }
        __syncthreads();
        if (tid < 128) {
            float vp = 0.f;
            #pragma unroll
            for (int x = 0; x < 16; x++) vp += vp_part[tid][x];
            g_r[bb * H_ + tid] = vp;
        }
    }
}

// =====================================================================
// Kernel 3: r2 = r @ Wrp + brp
// =====================================================================
__global__ void __launch_bounds__(256, 1) rproj_kernel(
    const float* __restrict__ Wrp, const float* __restrict__ brp)
{
    extern __shared__ float smf[];
    float* Rs = smf;
    float* Ws = smf + 64 * 132;
    const int tid = threadIdx.x, ty = tid >> 4, tx = tid & 15;
    const int m0 = blockIdx.x * 64;

    for (int i = tid; i < 64 * 128; i += 256) {
        int r = i >> 7, c = i & 127;
        Rs[r * 132 + c] = g_r[(m0 + r) * H_ + c];
    }
    for (int i = tid; i < 128 * 128; i += 256) Ws[i] = Wrp[i];
    __syncthreads();

    float acc[4][8];
    #pragma unroll
    for (int r = 0; r < 4; r++)
        #pragma unroll
        for (int j = 0; j < 8; j++) acc[r][j] = 0.f;
    #pragma unroll 8
    for (int k = 0; k < 128; k++) {
        float a[4], bbv[8];
        #pragma unroll
        for (int r = 0; r < 4; r++) a[r] = Rs[(ty * 4 + r) * 132 + k];
        #pragma unroll
        for (int j = 0; j < 8; j++) bbv[j] = Ws[k * 128 + tx + 16 * j];
        #pragma unroll
        for (int r = 0; r < 4; r++)
            #pragma unroll
            for (int j = 0; j < 8; j++) acc[r][j] = fmaf(a[r], bbv[j], acc[r][j]);
    }
    #pragma unroll
    for (int r = 0; r < 4; r++)
        #pragma unroll
        for (int j = 0; j < 8; j++) {
            int rr = m0 + ty * 4 + r, cc = tx + 16 * j;
            g_r2[rr * H_ + cc] = acc[r][j] + brp[cc];
        }
}

// =====================================================================
// Kernel 4: out = r2 @ Wout + bout
// =====================================================================
__global__ void __launch_bounds__(256, 1) out_kernel(
    const float* __restrict__ Wout, const float* __restrict__ bout,
    float* __restrict__ out)
{
    extern __shared__ float smf[];
    float* Rs = smf;
    float* Ws = smf + 64 * 132;
    const int tid = threadIdx.x, ty = tid >> 4, tx = tid & 15;
    const int n0 = blockIdx.x * 128;
    const int m0 = blockIdx.y * 64;

    for (int i = tid; i < 64 * 128; i += 256) {
        int r = i >> 7, c = i & 127;
        Rs[r * 132 + c] = g_r2[(m0 + r) * H_ + c];
    }
    for (int i = tid; i < 128 * 128; i += 256) {
        int k = i >> 7, c = i & 127;
        Ws[i] = Wout[(size_t)k * V_ + n0 + c];
    }
    __syncthreads();

    float acc[4][8];
    #pragma unroll
    for (int r = 0; r < 4; r++)
        #pragma unroll
        for (int j = 0; j < 8; j++) acc[r][j] = 0.f;
    #pragma unroll 8
    for (int k = 0; k < 128; k++) {
        float a[4], bbv[8];
        #pragma unroll
        for (int r = 0; r < 4; r++) a[r] = Rs[(ty * 4 + r) * 132 + k];
        #pragma unroll
        for (int j = 0; j < 8; j++) bbv[j] = Ws[k * 128 + tx + 16 * j];
        #pragma unroll
        for (int r = 0; r < 4; r++)
            #pragma unroll
            for (int j = 0; j < 8; j++) acc[r][j] = fmaf(a[r], bbv[j], acc[r][j]);
    }
    #pragma unroll
    for (int r = 0; r < 4; r++)
        #pragma unroll
        for (int j = 0; j < 8; j++) {
            int rr = m0 + ty * 4 + r, cc = n0 + tx + 16 * j;
            out[(size_t)rr * V_ + cc] = acc[r][j] + bout[cc];
        }
}

// =====================================================================
// launcher
// =====================================================================
extern "C" void kernel_launch(void* const* d_in, const int* in_sizes, int n_in,
                              void* d_out, int out_size)
{
    const int*   seq   = (const int*)  d_in[0];
    const float* embed = (const float*)d_in[1];
    const float* W1    = (const float*)d_in[2];
    const float* b1    = (const float*)d_in[3];
    const float* W2    = (const float*)d_in[4];
    const float* b2    = (const float*)d_in[5];
    const float* gamma = (const float*)d_in[6];
    const float* beta  = (const float*)d_in[7];
    const float* Wrp   = (const float*)d_in[8];
    const float* brp   = (const float*)d_in[9];
    const float* Wout  = (const float*)d_in[10];
    const float* bout  = (const float*)d_in[11];
    float* out = (float*)d_out;

    const int PROJ_SMEM = (64 * 132 + 128 * 128) * 4;

    cudaFuncSetAttribute(encode_ffma2, cudaFuncAttributeMaxDynamicSharedMemorySize, ENC_SMEM);
    cudaFuncSetAttribute(rproj_kernel, cudaFuncAttributeMaxDynamicSharedMemorySize, PROJ_SMEM);
    cudaFuncSetAttribute(out_kernel,   cudaFuncAttributeMaxDynamicSharedMemorySize, PROJ_SMEM);

    // profiling alignment: keep ncu's -s 5 window on encode_ffma2
    dummy_kernel<<<1, 32>>>();
    dummy_kernel<<<1, 32>>>();
    dummy_kernel<<<1, 32>>>();

    encode_ffma2<<<(B_ * L_) / TB, 256, ENC_SMEM>>>(seq, embed, W1, b1, W2, b2, gamma, beta);
    scan_kernel<<<B_, 256>>>();
    rproj_kernel<<<B_ / 64, 256, PROJ_SMEM>>>(Wrp, brp);
    out_kernel<<<dim3(V_ / 128, B_ / 64), 256, PROJ_SMEM>>>(Wout, bout, out);
}